// round 14
// baseline (speedup 1.0000x reference)
#include <cuda_runtime.h>
#include <cuda_bf16.h>
#include <math.h>

// Problem constants
#define B_  32
#define C_  256
#define O_  256
#define HH  56
#define WW  56
#define NT  784          // 28*28 Winograd output tiles (2x2 each)
#define TW  28

typedef unsigned int u32;

// ---------------- device scratch (no dynamic allocation allowed) ------------
__device__ float g_pooled[B_ * C_];                  // [b][c]
__device__ float g_kern[B_ * C_ * 4];                // [b][c*4+ch]
__device__ float g_wT[C_ * 9 * O_];                  // [c*9+ij][o]
__device__ u32   g_U[(size_t)B_ * 16 * 128 * O_];    // [b][t][cp][o]  f16x2 over c-pair
__device__ u32   g_V[(size_t)B_ * 16 * 128 * NT];    // [b][t][cp][n]  f16x2 over c-pair

// ---------------- helpers ---------------------------------------------------
__device__ __forceinline__ u32 smaddr(const void* p) {
    return (u32)__cvta_generic_to_shared(p);
}
__device__ __forceinline__ void cp16(u32 dst, const void* src) {
    asm volatile("cp.async.cg.shared.global [%0], [%1], 16;" :: "r"(dst), "l"(src));
}
__device__ __forceinline__ void cp_commit() { asm volatile("cp.async.commit_group;"); }
template <int N> __device__ __forceinline__ void cp_wait() {
    asm volatile("cp.async.wait_group %0;" :: "n"(N));
}
// pack {lo, hi} -> f16x2 (cvt.rn.f16x2.f32 d, a, b => d = {lo=b, hi=a})
__device__ __forceinline__ u32 packh2(float hi, float lo) {
    u32 d;
    asm("cvt.rn.f16x2.f32 %0, %1, %2;" : "=r"(d) : "f"(hi), "f"(lo));
    return d;
}
__device__ __forceinline__ void mma_f16(float* c, const u32* a, u32 b0, u32 b1) {
    asm volatile(
        "mma.sync.aligned.m16n8k16.row.col.f32.f16.f16.f32 "
        "{%0,%1,%2,%3}, {%4,%5,%6,%7}, {%8,%9}, {%0,%1,%2,%3};"
        : "+f"(c[0]), "+f"(c[1]), "+f"(c[2]), "+f"(c[3])
        : "r"(a[0]), "r"(a[1]), "r"(a[2]), "r"(a[3]), "r"(b0), "r"(b1));
}

// ---------------- K1: global average pool ------------------------------------
__global__ void pool_kernel(const float* __restrict__ x) {
    int bc = blockIdx.x;
    const float* p = x + (size_t)bc * (HH * WW);
    float s = 0.f;
    for (int i = threadIdx.x; i < HH * WW; i += 256) s += p[i];
    __shared__ float red[256];
    red[threadIdx.x] = s;
    __syncthreads();
    for (int st = 128; st > 0; st >>= 1) {
        if (threadIdx.x < st) red[threadIdx.x] += red[threadIdx.x + st];
        __syncthreads();
    }
    if (threadIdx.x == 0) g_pooled[bc] = red[0] * (1.f / (HH * WW));
}

// ---------------- K2: fc1(relu) + fc2 fused ----------------------------------
__global__ void fc_kernel(const float* __restrict__ fc1w,
                          const float* __restrict__ fc2w,
                          const float* __restrict__ fc2b) {
    int b = blockIdx.x, t = threadIdx.x;
    __shared__ float sp[C_], sh[C_];
    sp[t] = g_pooled[b * C_ + t];
    __syncthreads();
    float d = 0.f;
    const float* w1 = fc1w + t * C_;
    #pragma unroll 8
    for (int k = 0; k < C_; k++) d += sp[k] * w1[k];
    sh[t] = fmaxf(d, 0.f);
    __syncthreads();
    #pragma unroll
    for (int r = 0; r < 4; r++) {
        int j = r * 256 + t;
        const float* w2 = fc2w + j * C_;
        float d2 = fc2b[j];
        #pragma unroll 8
        for (int k = 0; k < C_; k++) d2 += sh[k] * w2[k];
        g_kern[b * (C_ * 4) + j] = d2;
    }
}

// ---------------- K2.5: transpose weight [o][c][ij] -> [c*9+ij][o] -----------
__global__ void wt_kernel(const float* __restrict__ w) {
    int e = blockIdx.x * 256 + threadIdx.x;
    int o = e / (C_ * 9);
    int rem = e - o * (C_ * 9);
    g_wT[(size_t)rem * O_ + o] = w[e];
}

// ---------------- K3: dyn weight + Winograd U transform ----------------------
// 4 c-pairs per block (amortize cogs smem fill); fast sigmoid via __expf.
__global__ void uwino_kernel(const float* __restrict__ cog) {
    const int cpg = blockIdx.x;       // 0..31
    const int b   = blockIdx.y;
    const int o   = threadIdx.x;      // 256
    __shared__ float cogs[36 * 256];  // [ch*9+ij][o]
    __shared__ float ks[1024];
    for (int e = o; e < 36 * 256; e += 256) {
        int kk = e >> 8, oo = e & 255;
        cogs[e] = cog[oo * 36 + kk];
    }
    for (int e = o; e < 1024; e += 256) ks[e] = g_kern[b * 1024 + e];
    __syncthreads();

    for (int ci = 0; ci < 4; ci++) {
        const int cp = cpg * 4 + ci;
        float U[2][16];
        #pragma unroll
        for (int h = 0; h < 2; h++) {
            const int c = 2 * cp + h;
            float g[9];
            #pragma unroll
            for (int ij = 0; ij < 9; ij++) {
                float s = ks[c * 4 + 0] * cogs[(0 + ij) * 256 + o]
                        + ks[c * 4 + 1] * cogs[(9 + ij) * 256 + o]
                        + ks[c * 4 + 2] * cogs[(18 + ij) * 256 + o]
                        + ks[c * 4 + 3] * cogs[(27 + ij) * 256 + o];
                g[ij] = (1.f / (1.f + __expf(-s))) * g_wT[(size_t)(c * 9 + ij) * O_ + o];
            }
            float q[4][3];
            #pragma unroll
            for (int j = 0; j < 3; j++) {
                q[0][j] = g[0 * 3 + j];
                q[1][j] = 0.5f * (g[0 * 3 + j] + g[1 * 3 + j] + g[2 * 3 + j]);
                q[2][j] = 0.5f * (g[0 * 3 + j] - g[1 * 3 + j] + g[2 * 3 + j]);
                q[3][j] = g[2 * 3 + j];
            }
            #pragma unroll
            for (int i = 0; i < 4; i++) {
                U[h][i * 4 + 0] = q[i][0];
                U[h][i * 4 + 1] = 0.5f * (q[i][0] + q[i][1] + q[i][2]);
                U[h][i * 4 + 2] = 0.5f * (q[i][0] - q[i][1] + q[i][2]);
                U[h][i * 4 + 3] = q[i][2];
            }
        }
        u32* dst = g_U + ((size_t)b * 16) * (128 * 256) + cp * 256 + o;
        #pragma unroll
        for (int t = 0; t < 16; t++)
            dst[(size_t)t * (128 * 256)] = packh2(U[1][t], U[0][t]);
    }
}

// ---------------- K4: Winograd input transform V = B^T d B --------------------
__global__ void vwino_kernel(const float* __restrict__ x) {
    const int n  = blockIdx.x * 256 + threadIdx.x;
    const int cp = blockIdx.y;
    const int b  = blockIdx.z;
    if (n >= NT) return;
    const int ty = n / TW, tx = n - ty * TW;
    const int r0 = 2 * ty - 1, q0 = 2 * tx - 1;

    float V[2][16];
    #pragma unroll
    for (int h = 0; h < 2; h++) {
        const int c = 2 * cp + h;
        const float* xp = x + ((size_t)b * C_ + c) * (HH * WW);
        float d[4][4];
        #pragma unroll
        for (int r = 0; r < 4; r++) {
            const int gr = r0 + r;
            #pragma unroll
            for (int j = 0; j < 4; j++) {
                const int gc = q0 + j;
                d[r][j] = ((unsigned)gr < HH && (unsigned)gc < WW)
                        ? xp[gr * WW + gc] : 0.f;
            }
        }
        float z[4][4];
        #pragma unroll
        for (int j = 0; j < 4; j++) {
            z[0][j] = d[0][j] - d[2][j];
            z[1][j] = d[1][j] + d[2][j];
            z[2][j] = d[2][j] - d[1][j];
            z[3][j] = d[1][j] - d[3][j];
        }
        #pragma unroll
        for (int i = 0; i < 4; i++) {
            V[h][i * 4 + 0] = z[i][0] - z[i][2];
            V[h][i * 4 + 1] = z[i][1] + z[i][2];
            V[h][i * 4 + 2] = z[i][2] - z[i][1];
            V[h][i * 4 + 3] = z[i][1] - z[i][3];
        }
    }
    u32* dst = g_V + ((size_t)b * 16) * (128 * NT) + cp * NT + n;
    #pragma unroll
    for (int t = 0; t < 16; t++)
        dst[(size_t)t * (128 * NT)] = packh2(V[1][t], V[0][t]);
}

// ---------------- K5: fused Winograd GEMM + output transform ------------------
// Block: 128 o x 56 n. 8 warps, warp = 16 o x 56 n. Loop t=0..15:
//   M_t[o][n] = sum_kp U_t[kp][o] V_t[kp][n]  (8 chunks of 16 kp, m16n8k16)
//   y[dy][dx] += A[i][dy]A[j][dx] * M_t   (t = i*4+j; coefs in {0,+-1})
// Write out directly; g_M intermediate eliminated.
#define AP 136                 // A pitch (words), 136%32=8 -> conflict-free
#define VP 56                  // V pitch, 56%32=24 -> conflict-free
#define SA_W (16 * AP)         // 2176
#define SV_W (16 * VP)         // 896
#define STG_W (SA_W + SV_W)    // 3072 words = 12 KB/stage

__global__ __launch_bounds__(256, 1)
void wgemm_kernel(float* __restrict__ out) {
    const int nb = blockIdx.x;             // 0..13 (56-n tile)
    const int mo = blockIdx.y;             // 0..1  (128-o tile)
    const int b  = blockIdx.z;
    const int o0 = mo * 128, n0 = nb * 56;

    const int tid  = threadIdx.x;
    const int wid  = tid >> 5, lane = tid & 31;
    const int grp = lane >> 2, qid = lane & 3;
    const int obase = wid * 16;            // warp's 16-o slice within tile

    __shared__ u32 sm[2 * STG_W];

    const u32* aG = g_U + ((size_t)b * 16) * (128 * 256) + o0;
    const u32* vG = g_V + ((size_t)b * 16) * (128 * NT) + n0;

    float macc[7][4];
    float y[7][4][4];
    #pragma unroll
    for (int nt = 0; nt < 7; nt++)
        #pragma unroll
        for (int r = 0; r < 4; r++) {
            macc[nt][r] = 0.f;
            y[nt][r][0] = y[nt][r][1] = y[nt][r][2] = y[nt][r][3] = 0.f;
        }

    // stage iteration g: t = g>>3, chunk it = g&7 (16 kp each)
    auto stage = [&](int g, int buf) {
        const int t = g >> 3, it = g & 7;
        u32* s = sm + buf * STG_W;
        const u32* aS = aG + ((size_t)t * 128 + it * 16) * 256;
        const u32* vS = vG + ((size_t)t * 128 + it * 16) * NT;
        #pragma unroll
        for (int e = tid; e < 512; e += 256) {       // A: 16 kp x 32 cp16
            int kp = e >> 5, q = e & 31;
            cp16(smaddr(s + kp * AP + q * 4), aS + (size_t)kp * 256 + q * 4);
        }
        if (tid < 224) {                              // V: 16 kp x 14 cp16
            int kp = tid / 14, q = tid - kp * 14;
            cp16(smaddr(s + SA_W + kp * VP + q * 4), vS + (size_t)kp * NT + q * 4);
        }
    };

    stage(0, 0);
    cp_commit();

    for (int g = 0; g < 128; g++) {
        const int buf = g & 1;
        if (g + 1 < 128) {
            stage(g + 1, buf ^ 1);
            cp_commit();
            cp_wait<1>();
        } else {
            cp_wait<0>();
        }
        __syncthreads();

        const u32* sA = sm + buf * STG_W;
        const u32* sV = sA + SA_W;

        #pragma unroll
        for (int s = 0; s < 2; s++) {
            const u32* pa = sA + (8 * s + qid) * AP + obase + grp;
            u32 a[4];
            a[0] = pa[0];
            a[1] = pa[8];
            a[2] = pa[4 * AP];
            a[3] = pa[4 * AP + 8];
            const u32* pv = sV + (8 * s + qid) * VP + grp;
            #pragma unroll
            for (int nt = 0; nt < 7; nt++) {
                u32 b0 = pv[nt * 8];
                u32 b1 = pv[4 * VP + nt * 8];
                mma_f16(macc[nt], a, b0, b1);
            }
        }
        __syncthreads();

        if ((g & 7) == 7) {                 // t complete: fold into y, reset M
            const int t = g >> 3;
            const int i = t >> 2, j = t & 3;
            const float ai0 = (i == 3) ? 0.f : 1.f;
            const float ai1 = (i == 0) ? 0.f : ((i == 1) ? 1.f : -1.f);
            const float aj0 = (j == 3) ? 0.f : 1.f;
            const float aj1 = (j == 0) ? 0.f : ((j == 1) ? 1.f : -1.f);
            const float c00 = ai0 * aj0, c01 = ai0 * aj1;
            const float c10 = ai1 * aj0, c11 = ai1 * aj1;
            #pragma unroll
            for (int nt = 0; nt < 7; nt++)
                #pragma unroll
                for (int r = 0; r < 4; r++) {
                    const float m = macc[nt][r];
                    y[nt][r][0] += c00 * m;
                    y[nt][r][1] += c01 * m;
                    y[nt][r][2] += c10 * m;
                    y[nt][r][3] += c11 * m;
                    macc[nt][r] = 0.f;
                }
        }
    }

    // ---- write output: frag (r) -> o row, n col; n -> (ty,tx) 2x2 tile ----
    #pragma unroll
    for (int nt = 0; nt < 7; nt++)
        #pragma unroll
        for (int r = 0; r < 4; r++) {
            const int o_r = o0 + obase + grp + ((r >> 1) ? 8 : 0);
            const int n_c = n0 + nt * 8 + 2 * qid + (r & 1);
            const int ty = n_c / TW, tx = n_c - ty * TW;
            float* op = out + (((size_t)b * O_ + o_r) * HH + 2 * ty) * WW + 2 * tx;
            *(float2*)op        = make_float2(y[nt][r][0], y[nt][r][1]);
            *(float2*)(op + WW) = make_float2(y[nt][r][2], y[nt][r][3]);
        }
}

// ---------------- launch ------------------------------------------------------
extern "C" void kernel_launch(void* const* d_in, const int* in_sizes, int n_in,
                              void* d_out, int out_size) {
    const float* x    = (const float*)d_in[0];   // [32,256,56,56]
    const float* fc1w = (const float*)d_in[1];   // [256,256]
    const float* fc2w = (const float*)d_in[2];   // [1024,256]
    const float* fc2b = (const float*)d_in[3];   // [1024]
    const float* cog  = (const float*)d_in[4];   // [256,4,3,3]
    const float* w    = (const float*)d_in[5];   // [256,256,3,3]
    float* out = (float*)d_out;                  // [32,256,56,56]

    pool_kernel<<<B_ * C_, 256>>>(x);
    fc_kernel<<<B_, 256>>>(fc1w, fc2w, fc2b);
    wt_kernel<<<(O_ * C_ * 9) / 256, 256>>>(w);
    uwino_kernel<<<dim3(32, 32), 256>>>(cog);
    vwino_kernel<<<dim3(4, 128, 32), 256>>>(x);
    wgemm_kernel<<<dim3(14, 2, 32), 256>>>(out);
}

// round 15
// speedup vs baseline: 1.2796x; 1.2796x over previous
#include <cuda_runtime.h>
#include <cuda_bf16.h>
#include <cuda_fp16.h>
#include <math.h>

// Problem constants
#define B_  32
#define C_  256
#define O_  256
#define HH  56
#define WW  56
#define NT  784          // 28*28 Winograd output tiles (2x2 each)
#define TW  28
#define NTH 392          // NT/2 n-pairs

typedef unsigned int u32;

// ---------------- device scratch (no dynamic allocation allowed) ------------
__device__ float g_pooled[B_ * C_];                  // [b][c]
__device__ float g_kern[B_ * C_ * 4];                // [b][c*4+ch]
__device__ float g_wT[C_ * 9 * O_];                  // [c*9+ij][o]
__device__ u32   g_U[(size_t)B_ * 16 * 128 * O_];    // [b][t][cp][o]  f16x2 over c-pair
__device__ u32   g_V[(size_t)B_ * 16 * 128 * NT];    // [b][t][cp][n]  f16x2 over c-pair
__device__ u32   g_M[(size_t)B_ * 16 * O_ * NTH];    // [b][t][o][np]  f16x2 over n-pair

// ---------------- helpers ---------------------------------------------------
__device__ __forceinline__ u32 smaddr(const void* p) {
    return (u32)__cvta_generic_to_shared(p);
}
__device__ __forceinline__ void cp16(u32 dst, const void* src) {
    asm volatile("cp.async.cg.shared.global [%0], [%1], 16;" :: "r"(dst), "l"(src));
}
__device__ __forceinline__ void cp_commit() { asm volatile("cp.async.commit_group;"); }
template <int N> __device__ __forceinline__ void cp_wait() {
    asm volatile("cp.async.wait_group %0;" :: "n"(N));
}
// pack {lo, hi} -> f16x2 (cvt.rn.f16x2.f32 d, a, b => d = {lo=b, hi=a})
__device__ __forceinline__ u32 packh2(float hi, float lo) {
    u32 d;
    asm("cvt.rn.f16x2.f32 %0, %1, %2;" : "=r"(d) : "f"(hi), "f"(lo));
    return d;
}
__device__ __forceinline__ void mma_f16(float* c, const u32* a, u32 b0, u32 b1) {
    asm volatile(
        "mma.sync.aligned.m16n8k16.row.col.f32.f16.f16.f32 "
        "{%0,%1,%2,%3}, {%4,%5,%6,%7}, {%8,%9}, {%0,%1,%2,%3};"
        : "+f"(c[0]), "+f"(c[1]), "+f"(c[2]), "+f"(c[3])
        : "r"(a[0]), "r"(a[1]), "r"(a[2]), "r"(a[3]), "r"(b0), "r"(b1));
}

// ---------------- K1: global average pool ------------------------------------
__global__ void pool_kernel(const float* __restrict__ x) {
    int bc = blockIdx.x;
    const float* p = x + (size_t)bc * (HH * WW);
    float s = 0.f;
    for (int i = threadIdx.x; i < HH * WW; i += 256) s += p[i];
    __shared__ float red[256];
    red[threadIdx.x] = s;
    __syncthreads();
    for (int st = 128; st > 0; st >>= 1) {
        if (threadIdx.x < st) red[threadIdx.x] += red[threadIdx.x + st];
        __syncthreads();
    }
    if (threadIdx.x == 0) g_pooled[bc] = red[0] * (1.f / (HH * WW));
}

// ---------------- K2: fc1(relu) + fc2 fused ----------------------------------
__global__ void fc_kernel(const float* __restrict__ fc1w,
                          const float* __restrict__ fc2w,
                          const float* __restrict__ fc2b) {
    int b = blockIdx.x, t = threadIdx.x;
    __shared__ float sp[C_], sh[C_];
    sp[t] = g_pooled[b * C_ + t];
    __syncthreads();
    float d = 0.f;
    const float* w1 = fc1w + t * C_;
    #pragma unroll 8
    for (int k = 0; k < C_; k++) d += sp[k] * w1[k];
    sh[t] = fmaxf(d, 0.f);
    __syncthreads();
    #pragma unroll
    for (int r = 0; r < 4; r++) {
        int j = r * 256 + t;
        const float* w2 = fc2w + j * C_;
        float d2 = fc2b[j];
        #pragma unroll 8
        for (int k = 0; k < C_; k++) d2 += sh[k] * w2[k];
        g_kern[b * (C_ * 4) + j] = d2;
    }
}

// ---------------- K2.5: transpose weight [o][c][ij] -> [c*9+ij][o] -----------
__global__ void wt_kernel(const float* __restrict__ w) {
    int e = blockIdx.x * 256 + threadIdx.x;
    int o = e / (C_ * 9);
    int rem = e - o * (C_ * 9);
    g_wT[(size_t)rem * O_ + o] = w[e];
}

// ---------------- K3: dyn weight + Winograd U transform ----------------------
// 4 c-pairs per block (amortize cogs fill); fast sigmoid via __expf.
__global__ void uwino_kernel(const float* __restrict__ cog) {
    const int cpg = blockIdx.x;       // 0..31
    const int b   = blockIdx.y;
    const int o   = threadIdx.x;      // 256
    __shared__ float cogs[36 * 256];  // [ch*9+ij][o]
    __shared__ float ks[1024];
    for (int e = o; e < 36 * 256; e += 256) {
        int kk = e >> 8, oo = e & 255;
        cogs[e] = cog[oo * 36 + kk];
    }
    for (int e = o; e < 1024; e += 256) ks[e] = g_kern[b * 1024 + e];
    __syncthreads();

    for (int ci = 0; ci < 4; ci++) {
        const int cp = cpg * 4 + ci;
        float U[2][16];
        #pragma unroll
        for (int h = 0; h < 2; h++) {
            const int c = 2 * cp + h;
            float g[9];
            #pragma unroll
            for (int ij = 0; ij < 9; ij++) {
                float s = ks[c * 4 + 0] * cogs[(0 + ij) * 256 + o]
                        + ks[c * 4 + 1] * cogs[(9 + ij) * 256 + o]
                        + ks[c * 4 + 2] * cogs[(18 + ij) * 256 + o]
                        + ks[c * 4 + 3] * cogs[(27 + ij) * 256 + o];
                g[ij] = (1.f / (1.f + __expf(-s))) * g_wT[(size_t)(c * 9 + ij) * O_ + o];
            }
            float q[4][3];
            #pragma unroll
            for (int j = 0; j < 3; j++) {
                q[0][j] = g[0 * 3 + j];
                q[1][j] = 0.5f * (g[0 * 3 + j] + g[1 * 3 + j] + g[2 * 3 + j]);
                q[2][j] = 0.5f * (g[0 * 3 + j] - g[1 * 3 + j] + g[2 * 3 + j]);
                q[3][j] = g[2 * 3 + j];
            }
            #pragma unroll
            for (int i = 0; i < 4; i++) {
                U[h][i * 4 + 0] = q[i][0];
                U[h][i * 4 + 1] = 0.5f * (q[i][0] + q[i][1] + q[i][2]);
                U[h][i * 4 + 2] = 0.5f * (q[i][0] - q[i][1] + q[i][2]);
                U[h][i * 4 + 3] = q[i][2];
            }
        }
        u32* dst = g_U + ((size_t)b * 16) * (128 * 256) + cp * 256 + o;
        #pragma unroll
        for (int t = 0; t < 16; t++)
            dst[(size_t)t * (128 * 256)] = packh2(U[1][t], U[0][t]);
    }
}

// ---------------- K4: Winograd input transform V = B^T d B --------------------
__global__ void vwino_kernel(const float* __restrict__ x) {
    const int n  = blockIdx.x * 256 + threadIdx.x;
    const int cp = blockIdx.y;
    const int b  = blockIdx.z;
    if (n >= NT) return;
    const int ty = n / TW, tx = n - ty * TW;
    const int r0 = 2 * ty - 1, q0 = 2 * tx - 1;

    float V[2][16];
    #pragma unroll
    for (int h = 0; h < 2; h++) {
        const int c = 2 * cp + h;
        const float* xp = x + ((size_t)b * C_ + c) * (HH * WW);
        float d[4][4];
        #pragma unroll
        for (int r = 0; r < 4; r++) {
            const int gr = r0 + r;
            #pragma unroll
            for (int j = 0; j < 4; j++) {
                const int gc = q0 + j;
                d[r][j] = ((unsigned)gr < HH && (unsigned)gc < WW)
                        ? xp[gr * WW + gc] : 0.f;
            }
        }
        float z[4][4];
        #pragma unroll
        for (int j = 0; j < 4; j++) {
            z[0][j] = d[0][j] - d[2][j];
            z[1][j] = d[1][j] + d[2][j];
            z[2][j] = d[2][j] - d[1][j];
            z[3][j] = d[1][j] - d[3][j];
        }
        #pragma unroll
        for (int i = 0; i < 4; i++) {
            V[h][i * 4 + 0] = z[i][0] - z[i][2];
            V[h][i * 4 + 1] = z[i][1] + z[i][2];
            V[h][i * 4 + 2] = z[i][2] - z[i][1];
            V[h][i * 4 + 3] = z[i][1] - z[i][3];
        }
    }
    u32* dst = g_V + ((size_t)b * 16) * (128 * NT) + cp * NT + n;
    #pragma unroll
    for (int t = 0; t < 16; t++)
        dst[(size_t)t * (128 * NT)] = packh2(V[1][t], V[0][t]);
}

// ---------------- K5: batched Winograd GEMM (fp16 m16n8k16) -------------------
// Per (b, t): M[256 o][784 n] = sum_cp U[cp][o] * V[cp][n], K = 128 pairs.
// Block: 128 o x 112 n, 8 warps (warp 32 o x 56 n), K chunks of 16 kp.
// Epilogue packs adjacent-n pairs to f16x2 -> g_M (halved traffic).
#define AP 136                 // A smem pitch (words): 136 % 32 = 8 -> conflict-free
#define VP 120                 // V smem pitch: 120 % 32 = 24 -> conflict-free
#define SA_W (16 * AP)         // 2176
#define SV_W (16 * VP)         // 1920
#define STG_W (SA_W + SV_W)    // 4096 words = 16 KB per stage

__global__ __launch_bounds__(256, 2)
void wgemm_kernel() {
    const int gx = blockIdx.x;             // 0..13
    const int nb = gx >> 1, mo = gx & 1;
    const int t = blockIdx.y, b = blockIdx.z;
    const int o0 = mo * 128, n0 = nb * 112;

    const int tid  = threadIdx.x;
    const int wid  = tid >> 5, lane = tid & 31;
    const int wm = wid & 3;                // 32-o quarter
    const int wn = wid >> 2;               // 56-n half
    const int grp = lane >> 2, qid = lane & 3;

    __shared__ u32 sm[2 * STG_W];

    const u32* aG = g_U + ((size_t)(b * 16 + t)) * (128 * 256) + o0;
    const u32* vG = g_V + ((size_t)(b * 16 + t)) * (128 * NT) + n0;

    float acc[2][7][4];
    #pragma unroll
    for (int mt = 0; mt < 2; mt++)
        #pragma unroll
        for (int nt = 0; nt < 7; nt++)
            #pragma unroll
            for (int r = 0; r < 4; r++) acc[mt][nt][r] = 0.f;

    // stage chunk 0
    {
        u32* s = sm;
        for (int e = tid; e < 512; e += 256) {
            int kp = e >> 5, q = e & 31;
            cp16(smaddr(s + kp * AP + q * 4), aG + kp * 256 + q * 4);
        }
        for (int e = tid; e < 448; e += 256) {
            int kp = e / 28, q = e - kp * 28;
            cp16(smaddr(s + SA_W + kp * VP + q * 4), vG + (size_t)kp * NT + q * 4);
        }
    }
    cp_commit();

    for (int it = 0; it < 8; it++) {
        if (it + 1 < 8) {
            u32* s = sm + ((it + 1) & 1) * STG_W;
            const u32* aS = aG + (it + 1) * 16 * 256;
            const u32* vS = vG + (size_t)(it + 1) * 16 * NT;
            for (int e = tid; e < 512; e += 256) {
                int kp = e >> 5, q = e & 31;
                cp16(smaddr(s + kp * AP + q * 4), aS + kp * 256 + q * 4);
            }
            for (int e = tid; e < 448; e += 256) {
                int kp = e / 28, q = e - kp * 28;
                cp16(smaddr(s + SA_W + kp * VP + q * 4), vS + (size_t)kp * NT + q * 4);
            }
            cp_commit();
            cp_wait<1>();
        } else {
            cp_wait<0>();
        }
        __syncthreads();

        const u32* sA = sm + (it & 1) * STG_W;
        const u32* sV = sA + SA_W;

        #pragma unroll
        for (int s = 0; s < 2; s++) {
            const u32* pa = sA + (8 * s + qid) * AP + wm * 32 + grp;
            u32 a[2][4];
            #pragma unroll
            for (int mt = 0; mt < 2; mt++) {
                const u32* pm = pa + mt * 16;
                a[mt][0] = pm[0];
                a[mt][1] = pm[8];
                a[mt][2] = pm[4 * AP];
                a[mt][3] = pm[4 * AP + 8];
            }
            const u32* pv = sV + (8 * s + qid) * VP + wn * 56 + grp;
            #pragma unroll
            for (int nt = 0; nt < 7; nt++) {
                u32 b0 = pv[nt * 8];
                u32 b1 = pv[4 * VP + nt * 8];
                mma_f16(acc[0][nt], a[0], b0, b1);
                mma_f16(acc[1][nt], a[1], b0, b1);
            }
        }
        __syncthreads();
    }

    // epilogue -> g_M f16x2 over adjacent n-pair (each thread owns cols 2qid, 2qid+1)
    #pragma unroll
    for (int mt = 0; mt < 2; mt++) {
        const int row = o0 + wm * 32 + mt * 16 + grp;
        u32* p0 = g_M + ((size_t)(b * 16 + t) * 256 + row) * NTH + (n0 + wn * 56) / 2;
        u32* p1 = p0 + 8 * NTH;
        #pragma unroll
        for (int nt = 0; nt < 7; nt++) {
            const int cp2 = nt * 4 + qid;
            p0[cp2] = packh2(acc[mt][nt][1], acc[mt][nt][0]);
            p1[cp2] = packh2(acc[mt][nt][3], acc[mt][nt][2]);
        }
    }
}

// ---------------- K6: output transform Y = A^T M A (per n-pair) ---------------
__global__ void yout_kernel(float* __restrict__ out) {
    const int np = blockIdx.x * 256 + threadIdx.x;     // n-pair 0..391
    const int o = blockIdx.y;
    const int b = blockIdx.z;
    if (np >= NTH) return;
    const u32* mp = g_M + ((size_t)(b * 16) * 256 + o) * NTH + np;
    float ma[16], mb[16];
    #pragma unroll
    for (int t = 0; t < 16; t++) {
        const u32 v = mp[(size_t)t * (256 * NTH)];
        const float2 f = __half22float2(*(const __half2*)&v);
        ma[t] = f.x;
        mb[t] = f.y;
    }
    float s0a[4], s1a[4], s0b[4], s1b[4];
    #pragma unroll
    for (int j = 0; j < 4; j++) {
        s0a[j] = ma[0 + j] + ma[4 + j] + ma[8 + j];
        s1a[j] = ma[4 + j] - ma[8 + j] - ma[12 + j];
        s0b[j] = mb[0 + j] + mb[4 + j] + mb[8 + j];
        s1b[j] = mb[4 + j] - mb[8 + j] - mb[12 + j];
    }
    const int n = 2 * np;
    const int ty = n / TW, tx = n - ty * TW;           // tx even
    float* op = out + ((size_t)(b * O_ + o) * HH + 2 * ty) * WW + 2 * tx;
    *(float4*)op = make_float4(
        s0a[0] + s0a[1] + s0a[2], s0a[1] - s0a[2] - s0a[3],
        s0b[0] + s0b[1] + s0b[2], s0b[1] - s0b[2] - s0b[3]);
    *(float4*)(op + WW) = make_float4(
        s1a[0] + s1a[1] + s1a[2], s1a[1] - s1a[2] - s1a[3],
        s1b[0] + s1b[1] + s1b[2], s1b[1] - s1b[2] - s1b[3]);
}

// ---------------- launch ------------------------------------------------------
extern "C" void kernel_launch(void* const* d_in, const int* in_sizes, int n_in,
                              void* d_out, int out_size) {
    const float* x    = (const float*)d_in[0];   // [32,256,56,56]
    const float* fc1w = (const float*)d_in[1];   // [256,256]
    const float* fc2w = (const float*)d_in[2];   // [1024,256]
    const float* fc2b = (const float*)d_in[3];   // [1024]
    const float* cog  = (const float*)d_in[4];   // [256,4,3,3]
    const float* w    = (const float*)d_in[5];   // [256,256,3,3]
    float* out = (float*)d_out;                  // [32,256,56,56]

    pool_kernel<<<B_ * C_, 256>>>(x);
    fc_kernel<<<B_, 256>>>(fc1w, fc2w, fc2b);
    wt_kernel<<<(O_ * C_ * 9) / 256, 256>>>(w);
    uwino_kernel<<<dim3(32, 32), 256>>>(cog);
    vwino_kernel<<<dim3(4, 128, 32), 256>>>(x);
    wgemm_kernel<<<dim3(14, 16, 32), 256>>>();
    yout_kernel<<<dim3(2, 256, 32), 256>>>(out);
}